// round 5
// baseline (speedup 1.0000x reference)
#include <cuda_runtime.h>
#include <cstdint>

#define BTc 16
#define Nc 1024
#define Dc 128
#define Hc 8
#define HDc 16
#define Mc (BTc*Nc)   // 16384 rows

// ---- scratch (no allocations allowed) ----
__device__ float g_q[(size_t)BTc*Hc*Nc*HDc];   // 8 MB, head-major, pre-scaled by log2e/4
__device__ float g_k[(size_t)BTc*Hc*Nc*HDc];   // 8 MB
__device__ float g_v[(size_t)BTc*Hc*Nc*HDc];   // 8 MB
__device__ float g_ctx[(size_t)Mc*Dc];         // 8 MB

// ---- packed f32x2 helpers (FFMA2 is PTX-only on sm_103a) ----
typedef unsigned long long f2_t;

__device__ __forceinline__ f2_t f2_mul(f2_t a, f2_t b){ f2_t r; asm("mul.rn.f32x2 %0,%1,%2;":"=l"(r):"l"(a),"l"(b)); return r; }
__device__ __forceinline__ f2_t f2_fma(f2_t a, f2_t b, f2_t c){ f2_t r; asm("fma.rn.f32x2 %0,%1,%2,%3;":"=l"(r):"l"(a),"l"(b),"l"(c)); return r; }
__device__ __forceinline__ f2_t f2_add(f2_t a, f2_t b){ f2_t r; asm("add.rn.f32x2 %0,%1,%2;":"=l"(r):"l"(a),"l"(b)); return r; }
__device__ __forceinline__ f2_t f2_pack(float lo, float hi){ f2_t r; asm("mov.b64 %0,{%1,%2};":"=l"(r):"f"(lo),"f"(hi)); return r; }
__device__ __forceinline__ void f2_unpack(f2_t a, float& lo, float& hi){ asm("mov.b64 {%0,%1},%2;":"=f"(lo),"=f"(hi):"l"(a)); }
__device__ __forceinline__ float fast_ex2(float x){ float r; asm("ex2.approx.f32 %0,%1;":"=f"(r):"f"(x)); return r; }

// ============================================================
// GEMM tile: 128 rows x 128 cols, K=128.  out = X @ W^T  (torch Linear)
// ============================================================
__device__ __forceinline__ void gemm_tile(const float* __restrict__ Xg,
                                          const float* __restrict__ Wg,
                                          float* Xs, float* Ws,
                                          f2_t acc2[8][4], int m0, int tid)
{
    #pragma unroll
    for (int it = 0; it < 16; ++it) {
        int idx = it*256 + tid;
        int m = idx >> 5, k4 = idx & 31;
        *(float4*)(Xs + m*132 + k4*4) = *(const float4*)(Xg + (size_t)(m0+m)*128 + k4*4);
        *(float4*)(Ws + m*132 + k4*4) = *(const float4*)(Wg + (size_t)m*128 + k4*4);
    }
    __syncthreads();

    int tx = tid & 15, ty = tid >> 4;
    #pragma unroll
    for (int i = 0; i < 8; ++i)
        #pragma unroll
        for (int t = 0; t < 4; ++t) acc2[i][t] = 0ULL;

    #pragma unroll 4
    for (int k = 0; k < 128; ++k) {
        f2_t a2[8], b2[4];
        #pragma unroll
        for (int i = 0; i < 8; ++i) {
            float a = Xs[(ty*8+i)*132 + k];
            a2[i] = f2_pack(a, a);
        }
        #pragma unroll
        for (int t = 0; t < 4; ++t) {
            float blo = Ws[(tx + 32*t)*132 + k];
            float bhi = Ws[(tx + 32*t + 16)*132 + k];
            b2[t] = f2_pack(blo, bhi);
        }
        #pragma unroll
        for (int i = 0; i < 8; ++i)
            #pragma unroll
            for (int t = 0; t < 4; ++t)
                acc2[i][t] = f2_fma(a2[i], b2[t], acc2[i][t]);
    }
}

// ============================================================
// QKV projection: grid (128, 3), 256 thr.  Writes head-major (bt,h,n,hd).
// ============================================================
__global__ void __launch_bounds__(256) proj_qkv_kernel(
    const float* __restrict__ x,
    const float* __restrict__ Wq, const float* __restrict__ bq,
    const float* __restrict__ Wk, const float* __restrict__ bk,
    const float* __restrict__ Wv, const float* __restrict__ bv)
{
    extern __shared__ float sm[];
    float* Xs = sm;
    float* Ws = sm + 128*132;

    int sel = blockIdx.y;
    const float* W    = (sel == 0) ? Wq : (sel == 1) ? Wk : Wv;
    const float* bias = (sel == 0) ? bq : (sel == 1) ? bk : bv;
    float*       out  = (sel == 0) ? g_q : (sel == 1) ? g_k : g_v;
    float scale = (sel == 0) ? (0.25f * 1.4426950408889634f) : 1.0f;

    int m0 = blockIdx.x * 128;
    f2_t acc2[8][4];
    gemm_tile(x, W, Xs, Ws, acc2, m0, threadIdx.x);

    int tx = threadIdx.x & 15, ty = threadIdx.x >> 4;
    int bt = m0 / Nc;
    int nbase = m0 % Nc;
    #pragma unroll
    for (int i = 0; i < 8; ++i) {
        int n = nbase + ty*8 + i;
        #pragma unroll
        for (int t = 0; t < 4; ++t) {
            float lo, hi; f2_unpack(acc2[i][t], lo, hi);
            int j0 = tx + 32*t, j1 = j0 + 16;
            float v0 = (lo + bias[j0]) * scale;
            float v1 = (hi + bias[j1]) * scale;
            out[(((size_t)bt*Hc + (j0 >> 4))*Nc + n)*HDc + (j0 & 15)] = v0;
            out[(((size_t)bt*Hc + (j1 >> 4))*Nc + n)*HDc + (j1 & 15)] = v1;
        }
    }
}

// ============================================================
// O projection
// ============================================================
__global__ void __launch_bounds__(256) proj_o_kernel(
    const float* __restrict__ Wo, const float* __restrict__ bo,
    float* __restrict__ out)
{
    extern __shared__ float sm[];
    float* Xs = sm;
    float* Ws = sm + 128*132;

    int m0 = blockIdx.x * 128;
    f2_t acc2[8][4];
    gemm_tile(g_ctx, Wo, Xs, Ws, acc2, m0, threadIdx.x);

    int tx = threadIdx.x & 15, ty = threadIdx.x >> 4;
    #pragma unroll
    for (int i = 0; i < 8; ++i) {
        size_t m = m0 + ty*8 + i;
        #pragma unroll
        for (int t = 0; t < 4; ++t) {
            float lo, hi; f2_unpack(acc2[i][t], lo, hi);
            int j0 = tx + 32*t, j1 = j0 + 16;
            out[m*Dc + j0] = lo + bo[j0];
            out[m*Dc + j1] = hi + bo[j1];
        }
    }
}

// ============================================================
// Fused attention v4: one CTA = one (bt, h) slab, 512 thr, R=2 rows/thr.
// 4 warps/SMSP (vs 2) for latency hiding; same fma-issue floor.
// adj double-buffered smem staging, 1 barrier/chunk.
// ============================================================
#define CHUNK 8
#define NCHUNK (Nc/CHUNK)         // 128
#define APAD 1028                 // %32==4 (conflict-free transpose STS)

__global__ void __launch_bounds__(512,1) attn_kernel(const float* __restrict__ adj)
{
    extern __shared__ float sm[];
    float* Ks = sm;                       // [1024][16]
    float* Vs = sm + Nc*HDc;              // [1024][16]
    float* Abuf = sm + 2*Nc*HDc;          // 2 x [CHUNK][APAD]

    int bt = blockIdx.x >> 3;
    int h  = blockIdx.x & 7;
    int slab = bt*Hc + h;
    int t = threadIdx.x;

    // ---- load K,V slab (coalesced) ----
    const float* kg = g_k + (size_t)slab*Nc*HDc;
    const float* vg = g_v + (size_t)slab*Nc*HDc;
    #pragma unroll
    for (int i = t; i < Nc*HDc/4; i += 512) {
        ((float4*)Ks)[i] = ((const float4*)kg)[i];
        ((float4*)Vs)[i] = ((const float4*)vg)[i];
    }

    // ---- load q for my 2 rows (pre-scaled by log2e/4) ----
    int r0 = 2*t;
    f2_t q2[2][8];
    const float* qp = g_q + ((size_t)slab*Nc + r0)*HDc;
    #pragma unroll
    for (int rr = 0; rr < 2; ++rr)
        #pragma unroll
        for (int j = 0; j < 4; ++j) {
            float4 f = *(const float4*)(qp + rr*HDc + j*4);
            q2[rr][2*j]   = f2_pack(f.x, f.y);
            q2[rr][2*j+1] = f2_pack(f.z, f.w);
        }

    f2_t acc2[2][8];
    #pragma unroll
    for (int rr = 0; rr < 2; ++rr)
        #pragma unroll
        for (int j = 0; j < 8; ++j) acc2[rr][j] = 0ULL;
    float sum[2] = {0.f, 0.f};

    // adj: chunk tile = [1024 rows][8 cols] = 2048 float4s, 4 per thread.
    // element e = it*512 + t  ->  row = e>>1, colgroup cq = e&1 (4 cols each)
    const float* ag = adj + (size_t)bt*Nc*Nc;
    float4 pf[4];
    #pragma unroll
    for (int it = 0; it < 4; ++it) {
        int e = it*512 + t;
        int r = e >> 1, cq = e & 1;
        pf[it] = *(const float4*)(ag + (size_t)r*Nc + 4*cq);
    }
    __syncthreads();   // K,V ready

    for (int chunk = 0; chunk < NCHUNK; ++chunk) {
        float* As = Abuf + (chunk & 1) * (CHUNK*APAD);

        // ---- store prefetched chunk transposed (conflict-free) ----
        #pragma unroll
        for (int it = 0; it < 4; ++it) {
            int e = it*512 + t;
            int r = e >> 1, cq = e & 1;
            As[(4*cq+0)*APAD + r] = pf[it].x;
            As[(4*cq+1)*APAD + r] = pf[it].y;
            As[(4*cq+2)*APAD + r] = pf[it].z;
            As[(4*cq+3)*APAD + r] = pf[it].w;
        }
        // ---- prefetch next chunk ----
        int nchunk = (chunk+1 < NCHUNK) ? (chunk+1) : 0;
        const float* agn = ag + nchunk*CHUNK;
        #pragma unroll
        for (int it = 0; it < 4; ++it) {
            int e = it*512 + t;
            int r = e >> 1, cq = e & 1;
            pf[it] = *(const float4*)(agn + (size_t)r*Nc + 4*cq);
        }
        __syncthreads();   // As writes visible; prior buffer reads complete

        int c0 = chunk*CHUNK;
        #pragma unroll 2
        for (int lc = 0; lc < CHUNK; ++lc) {
            int c = c0 + lc;
            const ulonglong2* kr = (const ulonglong2*)(Ks + c*HDc);
            ulonglong2 k0 = kr[0], k1 = kr[1], k2 = kr[2], k3 = kr[3];
            const ulonglong2* vr = (const ulonglong2*)(Vs + c*HDc);
            ulonglong2 v0 = vr[0], v1 = vr[1], v2 = vr[2], v3 = vr[3];
            // adj for my 2 rows at column c: one LDS.64
            float2 a2v = *(const float2*)(As + lc*APAD + r0);
            float aarr[2] = {a2v.x, a2v.y};

            #pragma unroll
            for (int rr = 0; rr < 2; ++rr) {
                // 9-op dot: two parallel chains
                f2_t d0 = f2_mul(q2[rr][0], k0.x);
                f2_t d1 = f2_mul(q2[rr][1], k0.y);
                d0 = f2_fma(q2[rr][2], k1.x, d0);
                d1 = f2_fma(q2[rr][3], k1.y, d1);
                d0 = f2_fma(q2[rr][4], k2.x, d0);
                d1 = f2_fma(q2[rr][5], k2.y, d1);
                d0 = f2_fma(q2[rr][6], k3.x, d0);
                d1 = f2_fma(q2[rr][7], k3.y, d1);
                d0 = f2_add(d0, d1);
                float lo, hi; f2_unpack(d0, lo, hi);
                float s = lo + hi;                 // log2-domain score

                float p = fast_ex2(s) * aarr[rr];  // MUFU pipe
                sum[rr] += p;
                f2_t pp = f2_pack(p, p);

                acc2[rr][0] = f2_fma(pp, v0.x, acc2[rr][0]);
                acc2[rr][1] = f2_fma(pp, v0.y, acc2[rr][1]);
                acc2[rr][2] = f2_fma(pp, v1.x, acc2[rr][2]);
                acc2[rr][3] = f2_fma(pp, v1.y, acc2[rr][3]);
                acc2[rr][4] = f2_fma(pp, v2.x, acc2[rr][4]);
                acc2[rr][5] = f2_fma(pp, v2.y, acc2[rr][5]);
                acc2[rr][6] = f2_fma(pp, v3.x, acc2[rr][6]);
                acc2[rr][7] = f2_fma(pp, v3.y, acc2[rr][7]);
            }
        }
        // no second barrier: double buffering separates writers/readers
    }

    // ---- write context ----
    #pragma unroll
    for (int rr = 0; rr < 2; ++rr) {
        float inv = 1.0f / sum[rr];
        float* outp = g_ctx + ((size_t)bt*Nc + r0 + rr)*Dc + h*HDc;
        #pragma unroll
        for (int j = 0; j < 4; ++j) {
            float lo0, hi0, lo1, hi1;
            f2_unpack(acc2[rr][2*j],   lo0, hi0);
            f2_unpack(acc2[rr][2*j+1], lo1, hi1);
            *(float4*)(outp + j*4) = make_float4(lo0*inv, hi0*inv, lo1*inv, hi1*inv);
        }
    }
}

// ============================================================
extern "C" void kernel_launch(void* const* d_in, const int* in_sizes, int n_in,
                              void* d_out, int out_size)
{
    const float* x   = (const float*)d_in[0];
    const float* adj = (const float*)d_in[1];
    const float* Wq  = (const float*)d_in[2];
    const float* bq  = (const float*)d_in[3];
    const float* Wk  = (const float*)d_in[4];
    const float* bk  = (const float*)d_in[5];
    const float* Wv  = (const float*)d_in[6];
    const float* bv  = (const float*)d_in[7];
    const float* Wo  = (const float*)d_in[8];
    const float* bo  = (const float*)d_in[9];
    float* out = (float*)d_out;

    const int smem_proj = 2 * 128 * 132 * sizeof(float);                    // 135168
    const int smem_attn = (2*Nc*HDc + 2*CHUNK*APAD) * sizeof(float);        // 196864
    cudaFuncSetAttribute(proj_qkv_kernel, cudaFuncAttributeMaxDynamicSharedMemorySize, smem_proj);
    cudaFuncSetAttribute(proj_o_kernel,   cudaFuncAttributeMaxDynamicSharedMemorySize, smem_proj);
    cudaFuncSetAttribute(attn_kernel,     cudaFuncAttributeMaxDynamicSharedMemorySize, smem_attn);

    dim3 gqkv(Mc/128, 3);
    proj_qkv_kernel<<<gqkv, 256, smem_proj>>>(x, Wq, bq, Wk, bk, Wv, bv);
    attn_kernel<<<BTc*Hc, 512, smem_attn>>>(adj);
    proj_o_kernel<<<Mc/128, 256, smem_proj>>>(Wo, bo, out);
}